// round 13
// baseline (speedup 1.0000x reference)
#include <cuda_runtime.h>

#define N_NODES 65536
#define NE      1048576
#define F_IN    16
#define HID     64
#define HEADS   4
#define PROJ    8
#define OUTD    128
#define BGR     512

// ---------------- scratch (static device globals; no allocation) -------------
__device__ float2   g_featH[N_NODES * 32];
__device__ float2   g_featA[N_NODES * 32];
__device__ float2   g_featB[N_NODES * 32];
__device__ float4   g_als4[N_NODES];
__device__ float4   g_ald4[N_NODES];
__device__ unsigned g_gmaxu[12];   // never zeroed: atomicMax over call-invariant data is idempotent
__device__ int      g_cnt[N_NODES];
__device__ int      g_rowptr[N_NODES + 1];
__device__ int      g_cursor[N_NODES];
__device__ int      g_bsum[64];
__device__ int      g_boff[64];
__device__ int      g_ssrc[NE];
__device__ float    g_pbuf[N_NODES * PROJ];

// host-side streams/events (host resources only; created once at load)
static cudaStream_t s_b;
static cudaEvent_t  ev_fork, ev_t16, ev_f0, ev_j0, ev_f1, ev_j1, ev_f2, ev_j2;
struct _StreamInit {
    _StreamInit() {
        cudaStreamCreateWithFlags(&s_b, cudaStreamNonBlocking);
        cudaEventCreateWithFlags(&ev_fork, cudaEventDisableTiming);
        cudaEventCreateWithFlags(&ev_t16,  cudaEventDisableTiming);
        cudaEventCreateWithFlags(&ev_f0,   cudaEventDisableTiming);
        cudaEventCreateWithFlags(&ev_j0,   cudaEventDisableTiming);
        cudaEventCreateWithFlags(&ev_f1,   cudaEventDisableTiming);
        cudaEventCreateWithFlags(&ev_j1,   cudaEventDisableTiming);
        cudaEventCreateWithFlags(&ev_f2,   cudaEventDisableTiming);
        cudaEventCreateWithFlags(&ev_j2,   cudaEventDisableTiming);
    }
};
static _StreamInit _sinit;

__device__ __forceinline__ float lrelu(float x) {
    return x > 0.f ? x : 0.2f * x;
}
__device__ __forceinline__ float sel4(float4 v, int h) {
    return h == 0 ? v.x : h == 1 ? v.y : h == 2 ? v.z : v.w;
}
__device__ __forceinline__ unsigned fenc(float f) {
    unsigned u = __float_as_uint(f);
    return (u & 0x80000000u) ? ~u : (u | 0x80000000u);
}
__device__ __forceinline__ float fdec(unsigned u) {
    return (u & 0x80000000u) ? __uint_as_float(u ^ 0x80000000u) : __uint_as_float(~u);
}

// ---------------- CSR build --------------------------------------------------
__global__ void k_zero_cnt() {
    int i = blockIdx.x * blockDim.x + threadIdx.x;
    if (i < N_NODES) g_cnt[i] = 0;
}

__global__ void k_count(const int* __restrict__ dst) {
    int e = blockIdx.x * blockDim.x + threadIdx.x;
    if (e < NE) atomicAdd(&g_cnt[dst[e]], 1);
}

__global__ void k_scan1() {
    __shared__ int sh[1024];
    int b = blockIdx.x, t = threadIdx.x, i = b * 1024 + t;
    int c = g_cnt[i];
    sh[t] = c;
    __syncthreads();
    for (int o = 1; o < 1024; o <<= 1) {
        int v = (t >= o) ? sh[t - o] : 0;
        __syncthreads();
        sh[t] += v;
        __syncthreads();
    }
    g_rowptr[i] = sh[t] - c;
    if (t == 1023) g_bsum[b] = sh[t];
}
__global__ void k_scan2() {
    __shared__ int sh[64];
    int t = threadIdx.x;
    int v = g_bsum[t];
    sh[t] = v;
    __syncthreads();
    for (int o = 1; o < 64; o <<= 1) {
        int u = (t >= o) ? sh[t - o] : 0;
        __syncthreads();
        sh[t] += u;
        __syncthreads();
    }
    g_boff[t] = sh[t] - v;
}
__global__ void k_scan3() {
    int b = blockIdx.x, t = threadIdx.x, i = b * 1024 + t;
    int r = g_rowptr[i] + g_boff[b];
    g_rowptr[i] = r;
    g_cursor[i] = r;
    if (i == 0) g_rowptr[N_NODES] = NE;
}

__global__ void k_scatter(const int* __restrict__ src, const int* __restrict__ dst) {
    int e = blockIdx.x * blockDim.x + threadIdx.x;
    if (e < NE) {
        int d = dst[e];
        int pos = atomicAdd(&g_cursor[d], 1);
        g_ssrc[pos] = src[e];
    }
}

// ---------------- dense transform --------------------------------------------
template <int K>
__global__ __launch_bounds__(256) void k_transform(const float* __restrict__ in,
                                                   const float* __restrict__ W,
                                                   const float* __restrict__ a_src,
                                                   const float* __restrict__ a_dst,
                                                   int layer) {
    __shared__ __align__(16) float Ws[K * 64];
    __shared__ __align__(16) float xs[32 * K];
    __shared__ float wm[8][4];
    int tid  = threadIdx.x;
    int w    = tid >> 5;
    int lane = tid & 31;
    int nblk = blockIdx.x * 32;

    for (int i = tid; i < K * 64; i += 256) Ws[i] = W[i];
    for (int i = tid; i < 32 * K; i += 256) xs[i] = in[nblk * K + i];
    __syncthreads();

    float2 acc[4];
#pragma unroll
    for (int n = 0; n < 4; n++) acc[n] = make_float2(0.f, 0.f);

    int nw = w * 4;
#pragma unroll
    for (int k = 0; k < K; k += 4) {
        float2 wv[4];
#pragma unroll
        for (int kk = 0; kk < 4; kk++)
            wv[kk] = *(const float2*)&Ws[(k + kk) * 64 + 2 * lane];
#pragma unroll
        for (int n = 0; n < 4; n++) {
            float4 xv = *(const float4*)&xs[(nw + n) * K + k];
            acc[n].x += xv.x * wv[0].x; acc[n].y += xv.x * wv[0].y;
            acc[n].x += xv.y * wv[1].x; acc[n].y += xv.y * wv[1].y;
            acc[n].x += xv.z * wv[2].x; acc[n].y += xv.z * wv[2].y;
            acc[n].x += xv.w * wv[3].x; acc[n].y += xv.w * wv[3].y;
        }
    }

    float as0 = a_src[2 * lane], as1 = a_src[2 * lane + 1];
    float ad0 = a_dst[2 * lane], ad1 = a_dst[2 * lane + 1];
    int head = lane >> 3;
    float vmax = -1e30f;
#pragma unroll
    for (int n = 0; n < 4; n++) {
        int node = nblk + nw + n;
        g_featH[node * 32 + lane] = acc[n];
        float vs = acc[n].x * as0 + acc[n].y * as1;
        float vd = acc[n].x * ad0 + acc[n].y * ad1;
#pragma unroll
        for (int o = 4; o >= 1; o >>= 1) {
            vs += __shfl_xor_sync(0xffffffffu, vs, o, 8);
            vd += __shfl_xor_sync(0xffffffffu, vd, o, 8);
        }
        if ((lane & 7) == 0) {
            ((float*)g_als4)[node * 4 + head] = vs;
            ((float*)g_ald4)[node * 4 + head] = vd;
            vmax = fmaxf(vmax, vs);
        }
    }
    if ((lane & 7) == 0) wm[w][head] = vmax;
    __syncthreads();
    if (w == 0) {
        float v = wm[lane >> 2][lane & 3];
#pragma unroll
        for (int o = 16; o >= 4; o >>= 1)
            v = fmaxf(v, __shfl_xor_sync(0xffffffffu, v, o));
        if (lane < 4) atomicMax(&g_gmaxu[layer * 4 + lane], fenc(v));
    }
}

// ---------------- aggregate core (R6 winner, byte-identical) ------------------
__device__ __forceinline__ float2 agg_core(int dst, int layer, int w, int lane,
                                           const float* __restrict__ bias,
                                           float4* ps_w) {
    int beg = g_rowptr[dst];
    int deg = g_rowptr[dst + 1] - beg;

    float b0 = bias[2 * lane];
    float b1 = bias[2 * lane + 1];

    if (deg == 0)
        return make_float2(fmaxf(b0, 0.f), fmaxf(b1, 0.f));

    float4 ald = g_ald4[dst];
    float4 C;
    C.x = lrelu(fdec(g_gmaxu[layer * 4 + 0]) + ald.x);
    C.y = lrelu(fdec(g_gmaxu[layer * 4 + 1]) + ald.y);
    C.z = lrelu(fdec(g_gmaxu[layer * 4 + 2]) + ald.z);
    C.w = lrelu(fdec(g_gmaxu[layer * 4 + 3]) + ald.w);

    int head = lane >> 3;
    float4 sum = make_float4(0.f, 0.f, 0.f, 0.f);
    float acc0 = 0.f, acc1 = 0.f;
    const float* pb = (const float*)ps_w;

    for (int base = 0; base < deg; base += 32) {
        int i = base + lane;
        bool v = i < deg;
        int s = g_ssrc[beg + (v ? i : deg - 1)];
        float4 a = g_als4[s];
        float4 p;
        p.x = v ? __expf(lrelu(a.x + ald.x) - C.x) : 0.f;
        p.y = v ? __expf(lrelu(a.y + ald.y) - C.y) : 0.f;
        p.z = v ? __expf(lrelu(a.z + ald.z) - C.z) : 0.f;
        p.w = v ? __expf(lrelu(a.w + ald.w) - C.w) : 0.f;
        sum.x += p.x; sum.y += p.y; sum.z += p.z; sum.w += p.w;
        ps_w[lane] = p;
        __syncwarp();

        int cnt = min(32, deg - base);
        int j = 0;
        for (; j + 8 <= cnt; j += 8) {
            int sj[8];
            float pj[8];
            float2 hv[8];
#pragma unroll
            for (int u = 0; u < 8; u++) sj[u] = __shfl_sync(0xffffffffu, s, j + u);
#pragma unroll
            for (int u = 0; u < 8; u++) pj[u] = pb[(j + u) * 4 + head];
#pragma unroll
            for (int u = 0; u < 8; u++) hv[u] = g_featH[sj[u] * 32 + lane];
#pragma unroll
            for (int u = 0; u < 8; u++) {
                acc0 += pj[u] * hv[u].x;
                acc1 += pj[u] * hv[u].y;
            }
        }
        for (; j + 4 <= cnt; j += 4) {
            int s0 = __shfl_sync(0xffffffffu, s, j + 0);
            int s1 = __shfl_sync(0xffffffffu, s, j + 1);
            int s2 = __shfl_sync(0xffffffffu, s, j + 2);
            int s3 = __shfl_sync(0xffffffffu, s, j + 3);
            float p0 = pb[(j + 0) * 4 + head];
            float p1 = pb[(j + 1) * 4 + head];
            float p2 = pb[(j + 2) * 4 + head];
            float p3 = pb[(j + 3) * 4 + head];
            float2 h0 = g_featH[s0 * 32 + lane];
            float2 h1 = g_featH[s1 * 32 + lane];
            float2 h2 = g_featH[s2 * 32 + lane];
            float2 h3 = g_featH[s3 * 32 + lane];
            acc0 += p0 * h0.x; acc1 += p0 * h0.y;
            acc0 += p1 * h1.x; acc1 += p1 * h1.y;
            acc0 += p2 * h2.x; acc1 += p2 * h2.y;
            acc0 += p3 * h3.x; acc1 += p3 * h3.y;
        }
        for (; j < cnt; j++) {
            int sj = __shfl_sync(0xffffffffu, s, j);
            float pj = pb[j * 4 + head];
            float2 hj = g_featH[sj * 32 + lane];
            acc0 += pj * hj.x; acc1 += pj * hj.y;
        }
        __syncwarp();
    }

#pragma unroll
    for (int o = 16; o >= 1; o >>= 1) {
        sum.x += __shfl_xor_sync(0xffffffffu, sum.x, o);
        sum.y += __shfl_xor_sync(0xffffffffu, sum.y, o);
        sum.z += __shfl_xor_sync(0xffffffffu, sum.z, o);
        sum.w += __shfl_xor_sync(0xffffffffu, sum.w, o);
    }
    float inv = 1.f / (sel4(sum, head) + 1e-16f);
    return make_float2(fmaxf(acc0 * inv + b0, 0.f),
                       fmaxf(acc1 * inv + b1, 0.f));
}

// boff: block offset (half-grid split across two streams)
__global__ __launch_bounds__(256) void k_aggregate(const float* __restrict__ bias,
                                                   int layer, int boff,
                                                   float2* __restrict__ out) {
    __shared__ float4 ps[8][32];
    int w    = threadIdx.x >> 5;
    int lane = threadIdx.x & 31;
    int dst  = (blockIdx.x + boff) * 8 + w;
    float2 o = agg_core(dst, layer, w, lane, bias, ps[w]);
    out[dst * 32 + lane] = o;
}

__global__ __launch_bounds__(256) void k_aggregate_proj(const float* __restrict__ bias,
                                                        int layer, int boff,
                                                        const float* __restrict__ Wp,
                                                        const float* __restrict__ bp) {
    __shared__ float4 ps[8][32];
    __shared__ float Wps[64 * PROJ];
    __shared__ float bps[PROJ];
    int tid  = threadIdx.x;
    int w    = tid >> 5;
    int lane = tid & 31;
    int dst  = (blockIdx.x + boff) * 8 + w;

    for (int i = tid; i < 64 * PROJ; i += 256) Wps[i] = Wp[i];
    if (tid < PROJ) bps[tid] = bp[tid];
    __syncthreads();

    float2 o = agg_core(dst, layer, w, lane, bias, ps[w]);

    float pr[PROJ];
#pragma unroll
    for (int p = 0; p < PROJ; p++)
        pr[p] = o.x * Wps[(2 * lane) * PROJ + p] + o.y * Wps[(2 * lane + 1) * PROJ + p];
#pragma unroll
    for (int off = 16; off >= 1; off >>= 1) {
#pragma unroll
        for (int p = 0; p < PROJ; p++)
            pr[p] += __shfl_xor_sync(0xffffffffu, pr[p], off);
    }
    if (lane == 0) {
        float4 r0 = make_float4(fmaxf(pr[0] + bps[0], 0.f), fmaxf(pr[1] + bps[1], 0.f),
                                fmaxf(pr[2] + bps[2], 0.f), fmaxf(pr[3] + bps[3], 0.f));
        float4 r1 = make_float4(fmaxf(pr[4] + bps[4], 0.f), fmaxf(pr[5] + bps[5], 0.f),
                                fmaxf(pr[6] + bps[6], 0.f), fmaxf(pr[7] + bps[7], 0.f));
        *(float4*)&g_pbuf[dst * PROJ]     = r0;
        *(float4*)&g_pbuf[dst * PROJ + 4] = r1;
    }
}

// ---------------- final GEMM: [512,1024] @ [1024,128] + bf -------------------
__global__ __launch_bounds__(256) void k_final(const float* __restrict__ Wf,
                                               const float* __restrict__ bf,
                                               float* __restrict__ out) {
    __shared__ float As[2 * 1024];
    __shared__ float red[2 * 128];
    int tid = threadIdx.x;
    int r0 = blockIdx.x * 2;
    for (int i = tid; i < 2 * 1024; i += 256) As[i] = g_pbuf[r0 * 1024 + i];
    __syncthreads();

    int col  = tid & 127;
    int half = tid >> 7;
    float acc[2] = {0.f, 0.f};
    int k0 = half * 512;
    for (int k = k0; k < k0 + 512; k += 8) {
#pragma unroll
        for (int kk = 0; kk < 8; kk++) {
            float wv = Wf[(k + kk) * 128 + col];
            acc[0] += As[k + kk] * wv;
            acc[1] += As[1024 + k + kk] * wv;
        }
    }
    if (half == 1) {
        red[col] = acc[0];
        red[128 + col] = acc[1];
    }
    __syncthreads();
    if (half == 0) {
        float bv = bf[col];
        out[r0 * 128 + col]       = acc[0] + red[col] + bv;
        out[(r0 + 1) * 128 + col] = acc[1] + red[128 + col] + bv;
    }
}

// ---------------- launch: fork-join DAG --------------------------------------
extern "C" void kernel_launch(void* const* d_in, const int* in_sizes, int n_in,
                              void* d_out, int out_size) {
    const float* x   = (const float*)d_in[0];
    const int*   ei  = (const int*)d_in[1];
    const int*   src = ei;
    const int*   dst = ei + NE;
    const float* W0  = (const float*)d_in[3];
    const float* as0 = (const float*)d_in[4];
    const float* ad0 = (const float*)d_in[5];
    const float* b0  = (const float*)d_in[6];
    const float* W1  = (const float*)d_in[7];
    const float* as1 = (const float*)d_in[8];
    const float* ad1 = (const float*)d_in[9];
    const float* b1  = (const float*)d_in[10];
    const float* W2  = (const float*)d_in[11];
    const float* as2 = (const float*)d_in[12];
    const float* ad2 = (const float*)d_in[13];
    const float* b2  = (const float*)d_in[14];
    const float* Wp  = (const float*)d_in[15];
    const float* bp  = (const float*)d_in[16];
    const float* Wf  = (const float*)d_in[17];
    const float* bf  = (const float*)d_in[18];
    float* out = (float*)d_out;

    // fork: branch B (t16) runs concurrently with the CSR chain (branch A)
    cudaEventRecord(ev_fork, 0);
    cudaStreamWaitEvent(s_b, ev_fork, 0);
    k_transform<F_IN><<<N_NODES / 32, 256, 0, s_b>>>(x, W0, as0, ad0, 0);
    cudaEventRecord(ev_t16, s_b);

    k_zero_cnt<<<N_NODES / 256, 256>>>();
    k_count<<<NE / 256, 256>>>(dst);
    k_scan1<<<64, 1024>>>();
    k_scan2<<<1, 64>>>();
    k_scan3<<<64, 1024>>>();
    k_scatter<<<NE / 256, 256>>>(src, dst);
    cudaStreamWaitEvent(0, ev_t16, 0);       // join

    // layer 0 aggregate: two concurrent half-grids
    cudaEventRecord(ev_f0, 0);
    cudaStreamWaitEvent(s_b, ev_f0, 0);
    k_aggregate<<<N_NODES / 16, 256>>>(b0, 0, 0, g_featA);
    k_aggregate<<<N_NODES / 16, 256, 0, s_b>>>(b0, 0, N_NODES / 16, g_featA);
    cudaEventRecord(ev_j0, s_b);
    cudaStreamWaitEvent(0, ev_j0, 0);

    k_transform<HID><<<N_NODES / 32, 256>>>((const float*)g_featA, W1, as1, ad1, 1);

    cudaEventRecord(ev_f1, 0);
    cudaStreamWaitEvent(s_b, ev_f1, 0);
    k_aggregate<<<N_NODES / 16, 256>>>(b1, 1, 0, g_featB);
    k_aggregate<<<N_NODES / 16, 256, 0, s_b>>>(b1, 1, N_NODES / 16, g_featB);
    cudaEventRecord(ev_j1, s_b);
    cudaStreamWaitEvent(0, ev_j1, 0);

    k_transform<HID><<<N_NODES / 32, 256>>>((const float*)g_featB, W2, as2, ad2, 2);

    cudaEventRecord(ev_f2, 0);
    cudaStreamWaitEvent(s_b, ev_f2, 0);
    k_aggregate_proj<<<N_NODES / 16, 256>>>(b2, 2, 0, Wp, bp);
    k_aggregate_proj<<<N_NODES / 16, 256, 0, s_b>>>(b2, 2, N_NODES / 16, Wp, bp);
    cudaEventRecord(ev_j2, s_b);
    cudaStreamWaitEvent(0, ev_j2, 0);

    k_final<<<BGR / 2, 256>>>(Wf, bf, out);
}

// round 14
// speedup vs baseline: 1.1105x; 1.1105x over previous
#include <cuda_runtime.h>

#define N_NODES 65536
#define NE      1048576
#define F_IN    16
#define HID     64
#define HEADS   4
#define PROJ    8
#define OUTD    128
#define BGR     512

// ---------------- scratch (static device globals; no allocation) -------------
__device__ float2   g_featH[N_NODES * 32];
__device__ float2   g_featA[N_NODES * 32];
__device__ float2   g_featB[N_NODES * 32];
__device__ float4   g_als4[N_NODES];
__device__ float4   g_ald4[N_NODES];
__device__ unsigned g_gmaxu[12];
__device__ int      g_cnt[N_NODES];
__device__ int      g_rowptr[N_NODES + 1];
__device__ int      g_cursor[N_NODES];
__device__ int      g_bsum[64];
__device__ int      g_boff[64];
__device__ int      g_ssrc[NE];
__device__ float    g_pbuf[N_NODES * PROJ];

__device__ __forceinline__ float lrelu(float x) {
    return x > 0.f ? x : 0.2f * x;
}
__device__ __forceinline__ float sel4(float4 v, int h) {
    return h == 0 ? v.x : h == 1 ? v.y : h == 2 ? v.z : v.w;
}
__device__ __forceinline__ unsigned fenc(float f) {
    unsigned u = __float_as_uint(f);
    return (u & 0x80000000u) ? ~u : (u | 0x80000000u);
}
__device__ __forceinline__ float fdec(unsigned u) {
    return (u & 0x80000000u) ? __uint_as_float(u ^ 0x80000000u) : __uint_as_float(~u);
}

// ---------------- CSR build --------------------------------------------------
__global__ void k_zero_cnt() {
    int i = blockIdx.x * blockDim.x + threadIdx.x;
    if (i < N_NODES) g_cnt[i] = 0;
    if (i < 12) g_gmaxu[i] = 0u;
}

__global__ void k_count(const int* __restrict__ dst) {
    int e = blockIdx.x * blockDim.x + threadIdx.x;
    if (e < NE) atomicAdd(&g_cnt[dst[e]], 1);
}

__global__ void k_scan1() {
    __shared__ int sh[1024];
    int b = blockIdx.x, t = threadIdx.x, i = b * 1024 + t;
    int c = g_cnt[i];
    sh[t] = c;
    __syncthreads();
    for (int o = 1; o < 1024; o <<= 1) {
        int v = (t >= o) ? sh[t - o] : 0;
        __syncthreads();
        sh[t] += v;
        __syncthreads();
    }
    g_rowptr[i] = sh[t] - c;
    if (t == 1023) g_bsum[b] = sh[t];
}
__global__ void k_scan2() {
    __shared__ int sh[64];
    int t = threadIdx.x;
    int v = g_bsum[t];
    sh[t] = v;
    __syncthreads();
    for (int o = 1; o < 64; o <<= 1) {
        int u = (t >= o) ? sh[t - o] : 0;
        __syncthreads();
        sh[t] += u;
        __syncthreads();
    }
    g_boff[t] = sh[t] - v;
}
__global__ void k_scan3() {
    int b = blockIdx.x, t = threadIdx.x, i = b * 1024 + t;
    int r = g_rowptr[i] + g_boff[b];
    g_rowptr[i] = r;
    g_cursor[i] = r;
    if (i == 0) g_rowptr[N_NODES] = NE;
}

__global__ void k_scatter(const int* __restrict__ src, const int* __restrict__ dst) {
    int e = blockIdx.x * blockDim.x + threadIdx.x;
    if (e < NE) {
        int d = dst[e];
        int pos = atomicAdd(&g_cursor[d], 1);
        g_ssrc[pos] = src[e];
    }
}

// ---------------- dense transform --------------------------------------------
template <int K>
__global__ __launch_bounds__(256) void k_transform(const float* __restrict__ in,
                                                   const float* __restrict__ W,
                                                   const float* __restrict__ a_src,
                                                   const float* __restrict__ a_dst,
                                                   int layer) {
    __shared__ __align__(16) float Ws[K * 64];
    __shared__ __align__(16) float xs[32 * K];
    __shared__ float wm[8][4];
    int tid  = threadIdx.x;
    int w    = tid >> 5;
    int lane = tid & 31;
    int nblk = blockIdx.x * 32;

    for (int i = tid; i < K * 64; i += 256) Ws[i] = W[i];
    for (int i = tid; i < 32 * K; i += 256) xs[i] = in[nblk * K + i];
    __syncthreads();

    float2 acc[4];
#pragma unroll
    for (int n = 0; n < 4; n++) acc[n] = make_float2(0.f, 0.f);

    int nw = w * 4;
#pragma unroll
    for (int k = 0; k < K; k += 4) {
        float2 wv[4];
#pragma unroll
        for (int kk = 0; kk < 4; kk++)
            wv[kk] = *(const float2*)&Ws[(k + kk) * 64 + 2 * lane];
#pragma unroll
        for (int n = 0; n < 4; n++) {
            float4 xv = *(const float4*)&xs[(nw + n) * K + k];
            acc[n].x += xv.x * wv[0].x; acc[n].y += xv.x * wv[0].y;
            acc[n].x += xv.y * wv[1].x; acc[n].y += xv.y * wv[1].y;
            acc[n].x += xv.z * wv[2].x; acc[n].y += xv.z * wv[2].y;
            acc[n].x += xv.w * wv[3].x; acc[n].y += xv.w * wv[3].y;
        }
    }

    float as0 = a_src[2 * lane], as1 = a_src[2 * lane + 1];
    float ad0 = a_dst[2 * lane], ad1 = a_dst[2 * lane + 1];
    int head = lane >> 3;
    float vmax = -1e30f;
#pragma unroll
    for (int n = 0; n < 4; n++) {
        int node = nblk + nw + n;
        g_featH[node * 32 + lane] = acc[n];
        float vs = acc[n].x * as0 + acc[n].y * as1;
        float vd = acc[n].x * ad0 + acc[n].y * ad1;
#pragma unroll
        for (int o = 4; o >= 1; o >>= 1) {
            vs += __shfl_xor_sync(0xffffffffu, vs, o, 8);
            vd += __shfl_xor_sync(0xffffffffu, vd, o, 8);
        }
        if ((lane & 7) == 0) {
            ((float*)g_als4)[node * 4 + head] = vs;
            ((float*)g_ald4)[node * 4 + head] = vd;
            vmax = fmaxf(vmax, vs);
        }
    }
    if ((lane & 7) == 0) wm[w][head] = vmax;
    __syncthreads();
    if (w == 0) {
        float v = wm[lane >> 2][lane & 3];
#pragma unroll
        for (int o = 16; o >= 4; o >>= 1)
            v = fmaxf(v, __shfl_xor_sync(0xffffffffu, v, o));
        if (lane < 4) atomicMax(&g_gmaxu[layer * 4 + lane], fenc(v));
    }
}

// ---------------- aggregate core (R6 winner, byte-identical) ------------------
__device__ __forceinline__ float2 agg_core(int dst, int layer, int w, int lane,
                                           const float* __restrict__ bias,
                                           float4* ps_w) {
    int beg = g_rowptr[dst];
    int deg = g_rowptr[dst + 1] - beg;

    float b0 = bias[2 * lane];
    float b1 = bias[2 * lane + 1];

    if (deg == 0)
        return make_float2(fmaxf(b0, 0.f), fmaxf(b1, 0.f));

    float4 ald = g_ald4[dst];
    float4 C;
    C.x = lrelu(fdec(g_gmaxu[layer * 4 + 0]) + ald.x);
    C.y = lrelu(fdec(g_gmaxu[layer * 4 + 1]) + ald.y);
    C.z = lrelu(fdec(g_gmaxu[layer * 4 + 2]) + ald.z);
    C.w = lrelu(fdec(g_gmaxu[layer * 4 + 3]) + ald.w);

    int head = lane >> 3;
    float4 sum = make_float4(0.f, 0.f, 0.f, 0.f);
    float acc0 = 0.f, acc1 = 0.f;
    const float* pb = (const float*)ps_w;

    for (int base = 0; base < deg; base += 32) {
        int i = base + lane;
        bool v = i < deg;
        int s = g_ssrc[beg + (v ? i : deg - 1)];
        float4 a = g_als4[s];
        float4 p;
        p.x = v ? __expf(lrelu(a.x + ald.x) - C.x) : 0.f;
        p.y = v ? __expf(lrelu(a.y + ald.y) - C.y) : 0.f;
        p.z = v ? __expf(lrelu(a.z + ald.z) - C.z) : 0.f;
        p.w = v ? __expf(lrelu(a.w + ald.w) - C.w) : 0.f;
        sum.x += p.x; sum.y += p.y; sum.z += p.z; sum.w += p.w;
        ps_w[lane] = p;
        __syncwarp();

        int cnt = min(32, deg - base);
        int j = 0;
        for (; j + 8 <= cnt; j += 8) {
            int sj[8];
            float pj[8];
            float2 hv[8];
#pragma unroll
            for (int u = 0; u < 8; u++) sj[u] = __shfl_sync(0xffffffffu, s, j + u);
#pragma unroll
            for (int u = 0; u < 8; u++) pj[u] = pb[(j + u) * 4 + head];
#pragma unroll
            for (int u = 0; u < 8; u++) hv[u] = g_featH[sj[u] * 32 + lane];
#pragma unroll
            for (int u = 0; u < 8; u++) {
                acc0 += pj[u] * hv[u].x;
                acc1 += pj[u] * hv[u].y;
            }
        }
        for (; j + 4 <= cnt; j += 4) {
            int s0 = __shfl_sync(0xffffffffu, s, j + 0);
            int s1 = __shfl_sync(0xffffffffu, s, j + 1);
            int s2 = __shfl_sync(0xffffffffu, s, j + 2);
            int s3 = __shfl_sync(0xffffffffu, s, j + 3);
            float p0 = pb[(j + 0) * 4 + head];
            float p1 = pb[(j + 1) * 4 + head];
            float p2 = pb[(j + 2) * 4 + head];
            float p3 = pb[(j + 3) * 4 + head];
            float2 h0 = g_featH[s0 * 32 + lane];
            float2 h1 = g_featH[s1 * 32 + lane];
            float2 h2 = g_featH[s2 * 32 + lane];
            float2 h3 = g_featH[s3 * 32 + lane];
            acc0 += p0 * h0.x; acc1 += p0 * h0.y;
            acc0 += p1 * h1.x; acc1 += p1 * h1.y;
            acc0 += p2 * h2.x; acc1 += p2 * h2.y;
            acc0 += p3 * h3.x; acc1 += p3 * h3.y;
        }
        for (; j < cnt; j++) {
            int sj = __shfl_sync(0xffffffffu, s, j);
            float pj = pb[j * 4 + head];
            float2 hj = g_featH[sj * 32 + lane];
            acc0 += pj * hj.x; acc1 += pj * hj.y;
        }
        __syncwarp();
    }

#pragma unroll
    for (int o = 16; o >= 1; o >>= 1) {
        sum.x += __shfl_xor_sync(0xffffffffu, sum.x, o);
        sum.y += __shfl_xor_sync(0xffffffffu, sum.y, o);
        sum.z += __shfl_xor_sync(0xffffffffu, sum.z, o);
        sum.w += __shfl_xor_sync(0xffffffffu, sum.w, o);
    }
    float inv = 1.f / (sel4(sum, head) + 1e-16f);
    return make_float2(fmaxf(acc0 * inv + b0, 0.f),
                       fmaxf(acc1 * inv + b1, 0.f));
}

// 6 blocks/SM forced (regs capped at 42) — occupancy experiment
__global__ __launch_bounds__(256, 6) void k_aggregate(const float* __restrict__ bias,
                                                      int layer,
                                                      float2* __restrict__ out) {
    __shared__ float4 ps[8][32];
    int w    = threadIdx.x >> 5;
    int lane = threadIdx.x & 31;
    int dst  = blockIdx.x * 8 + w;
    float2 o = agg_core(dst, layer, w, lane, bias, ps[w]);
    out[dst * 32 + lane] = o;
}

// layer-2 variant: fused node projection -> writes g_pbuf[n*8+p]
__global__ __launch_bounds__(256, 6) void k_aggregate_proj(const float* __restrict__ bias,
                                                           int layer,
                                                           const float* __restrict__ Wp,
                                                           const float* __restrict__ bp) {
    __shared__ float4 ps[8][32];
    __shared__ float Wps[64 * PROJ];
    __shared__ float bps[PROJ];
    int tid  = threadIdx.x;
    int w    = tid >> 5;
    int lane = tid & 31;
    int dst  = blockIdx.x * 8 + w;

    for (int i = tid; i < 64 * PROJ; i += 256) Wps[i] = Wp[i];
    if (tid < PROJ) bps[tid] = bp[tid];
    __syncthreads();

    float2 o = agg_core(dst, layer, w, lane, bias, ps[w]);

    float pr[PROJ];
#pragma unroll
    for (int p = 0; p < PROJ; p++)
        pr[p] = o.x * Wps[(2 * lane) * PROJ + p] + o.y * Wps[(2 * lane + 1) * PROJ + p];
#pragma unroll
    for (int off = 16; off >= 1; off >>= 1) {
#pragma unroll
        for (int p = 0; p < PROJ; p++)
            pr[p] += __shfl_xor_sync(0xffffffffu, pr[p], off);
    }
    if (lane == 0) {
        float4 r0 = make_float4(fmaxf(pr[0] + bps[0], 0.f), fmaxf(pr[1] + bps[1], 0.f),
                                fmaxf(pr[2] + bps[2], 0.f), fmaxf(pr[3] + bps[3], 0.f));
        float4 r1 = make_float4(fmaxf(pr[4] + bps[4], 0.f), fmaxf(pr[5] + bps[5], 0.f),
                                fmaxf(pr[6] + bps[6], 0.f), fmaxf(pr[7] + bps[7], 0.f));
        *(float4*)&g_pbuf[dst * PROJ]     = r0;
        *(float4*)&g_pbuf[dst * PROJ + 4] = r1;
    }
}

// ---------------- final GEMM: [512,1024] @ [1024,128] + bf -------------------
__global__ __launch_bounds__(256) void k_final(const float* __restrict__ Wf,
                                               const float* __restrict__ bf,
                                               float* __restrict__ out) {
    __shared__ float As[2 * 1024];
    __shared__ float red[2 * 128];
    int tid = threadIdx.x;
    int r0 = blockIdx.x * 2;
    for (int i = tid; i < 2 * 1024; i += 256) As[i] = g_pbuf[r0 * 1024 + i];
    __syncthreads();

    int col  = tid & 127;
    int half = tid >> 7;
    float acc[2] = {0.f, 0.f};
    int k0 = half * 512;
    for (int k = k0; k < k0 + 512; k += 8) {
#pragma unroll
        for (int kk = 0; kk < 8; kk++) {
            float wv = Wf[(k + kk) * 128 + col];
            acc[0] += As[k + kk] * wv;
            acc[1] += As[1024 + k + kk] * wv;
        }
    }
    if (half == 1) {
        red[col] = acc[0];
        red[128 + col] = acc[1];
    }
    __syncthreads();
    if (half == 0) {
        float bv = bf[col];
        out[r0 * 128 + col]       = acc[0] + red[col] + bv;
        out[(r0 + 1) * 128 + col] = acc[1] + red[128 + col] + bv;
    }
}

// ---------------- launch (R6 order; t16 in profiled slot 4) -------------------
extern "C" void kernel_launch(void* const* d_in, const int* in_sizes, int n_in,
                              void* d_out, int out_size) {
    const float* x   = (const float*)d_in[0];
    const int*   ei  = (const int*)d_in[1];
    const int*   src = ei;
    const int*   dst = ei + NE;
    const float* W0  = (const float*)d_in[3];
    const float* as0 = (const float*)d_in[4];
    const float* ad0 = (const float*)d_in[5];
    const float* b0  = (const float*)d_in[6];
    const float* W1  = (const float*)d_in[7];
    const float* as1 = (const float*)d_in[8];
    const float* ad1 = (const float*)d_in[9];
    const float* b1  = (const float*)d_in[10];
    const float* W2  = (const float*)d_in[11];
    const float* as2 = (const float*)d_in[12];
    const float* ad2 = (const float*)d_in[13];
    const float* b2  = (const float*)d_in[14];
    const float* Wp  = (const float*)d_in[15];
    const float* bp  = (const float*)d_in[16];
    const float* Wf  = (const float*)d_in[17];
    const float* bf  = (const float*)d_in[18];
    float* out = (float*)d_out;

    k_zero_cnt<<<N_NODES / 256, 256>>>();                              // 1
    k_count<<<NE / 256, 256>>>(dst);                                   // 2
    k_scan1<<<64, 1024>>>();                                           // 3
    k_transform<F_IN><<<N_NODES / 32, 256>>>(x, W0, as0, ad0, 0);      // 4 (profiled)
    k_scan2<<<1, 64>>>();                                              // 5
    k_scan3<<<64, 1024>>>();                                           // 6
    k_scatter<<<NE / 256, 256>>>(src, dst);                            // 7

    k_aggregate<<<N_NODES / 8, 256>>>(b0, 0, g_featA);                 // 8

    k_transform<HID><<<N_NODES / 32, 256>>>((const float*)g_featA, W1, as1, ad1, 1);
    k_aggregate<<<N_NODES / 8, 256>>>(b1, 1, g_featB);

    k_transform<HID><<<N_NODES / 32, 256>>>((const float*)g_featB, W2, as2, ad2, 2);
    k_aggregate_proj<<<N_NODES / 8, 256>>>(b2, 2, Wp, bp);

    k_final<<<BGR / 2, 256>>>(Wf, bf, out);
}

// round 15
// speedup vs baseline: 1.1142x; 1.0033x over previous
#include <cuda_runtime.h>

#define N_NODES 65536
#define NE      1048576
#define F_IN    16
#define HID     64
#define HEADS   4
#define PROJ    8
#define OUTD    128
#define BGR     512

// ---------------- scratch (static device globals; no allocation) -------------
__device__ float2   g_featH[N_NODES * 32];
__device__ float2   g_featA[N_NODES * 32];
__device__ float2   g_featB[N_NODES * 32];
__device__ float4   g_als4[N_NODES];
__device__ float4   g_ald4[N_NODES];
__device__ unsigned g_gmaxu[12];
__device__ int      g_cnt[N_NODES];
__device__ int      g_rowptr[N_NODES + 1];
__device__ int      g_cursor[N_NODES];
__device__ int      g_bsum[64];
__device__ int      g_boff[64];
__device__ int      g_ssrc[NE];
__device__ float    g_pbuf[N_NODES * PROJ];

__device__ __forceinline__ float lrelu(float x) {
    return x > 0.f ? x : 0.2f * x;
}
__device__ __forceinline__ unsigned fenc(float f) {
    unsigned u = __float_as_uint(f);
    return (u & 0x80000000u) ? ~u : (u | 0x80000000u);
}
__device__ __forceinline__ float fdec(unsigned u) {
    return (u & 0x80000000u) ? __uint_as_float(u ^ 0x80000000u) : __uint_as_float(~u);
}

// ---------------- CSR build --------------------------------------------------
__global__ void k_zero_cnt() {
    int i = blockIdx.x * blockDim.x + threadIdx.x;
    if (i < N_NODES) g_cnt[i] = 0;
    if (i < 12) g_gmaxu[i] = 0u;
}

__global__ void k_count(const int* __restrict__ dst) {
    int e = blockIdx.x * blockDim.x + threadIdx.x;
    if (e < NE) atomicAdd(&g_cnt[dst[e]], 1);
}

__global__ void k_scan1() {
    __shared__ int sh[1024];
    int b = blockIdx.x, t = threadIdx.x, i = b * 1024 + t;
    int c = g_cnt[i];
    sh[t] = c;
    __syncthreads();
    for (int o = 1; o < 1024; o <<= 1) {
        int v = (t >= o) ? sh[t - o] : 0;
        __syncthreads();
        sh[t] += v;
        __syncthreads();
    }
    g_rowptr[i] = sh[t] - c;
    if (t == 1023) g_bsum[b] = sh[t];
}
__global__ void k_scan2() {
    __shared__ int sh[64];
    int t = threadIdx.x;
    int v = g_bsum[t];
    sh[t] = v;
    __syncthreads();
    for (int o = 1; o < 64; o <<= 1) {
        int u = (t >= o) ? sh[t - o] : 0;
        __syncthreads();
        sh[t] += u;
        __syncthreads();
    }
    g_boff[t] = sh[t] - v;
}
__global__ void k_scan3() {
    int b = blockIdx.x, t = threadIdx.x, i = b * 1024 + t;
    int r = g_rowptr[i] + g_boff[b];
    g_rowptr[i] = r;
    g_cursor[i] = r;
    if (i == 0) g_rowptr[N_NODES] = NE;
}

__global__ void k_scatter(const int* __restrict__ src, const int* __restrict__ dst) {
    int e = blockIdx.x * blockDim.x + threadIdx.x;
    if (e < NE) {
        int d = dst[e];
        int pos = atomicAdd(&g_cursor[d], 1);
        g_ssrc[pos] = src[e];
    }
}

// ---------------- dense transform (unchanged) ---------------------------------
template <int K>
__global__ __launch_bounds__(256) void k_transform(const float* __restrict__ in,
                                                   const float* __restrict__ W,
                                                   const float* __restrict__ a_src,
                                                   const float* __restrict__ a_dst,
                                                   int layer) {
    __shared__ __align__(16) float Ws[K * 64];
    __shared__ __align__(16) float xs[32 * K];
    __shared__ float wm[8][4];
    int tid  = threadIdx.x;
    int w    = tid >> 5;
    int lane = tid & 31;
    int nblk = blockIdx.x * 32;

    for (int i = tid; i < K * 64; i += 256) Ws[i] = W[i];
    for (int i = tid; i < 32 * K; i += 256) xs[i] = in[nblk * K + i];
    __syncthreads();

    float2 acc[4];
#pragma unroll
    for (int n = 0; n < 4; n++) acc[n] = make_float2(0.f, 0.f);

    int nw = w * 4;
#pragma unroll
    for (int k = 0; k < K; k += 4) {
        float2 wv[4];
#pragma unroll
        for (int kk = 0; kk < 4; kk++)
            wv[kk] = *(const float2*)&Ws[(k + kk) * 64 + 2 * lane];
#pragma unroll
        for (int n = 0; n < 4; n++) {
            float4 xv = *(const float4*)&xs[(nw + n) * K + k];
            acc[n].x += xv.x * wv[0].x; acc[n].y += xv.x * wv[0].y;
            acc[n].x += xv.y * wv[1].x; acc[n].y += xv.y * wv[1].y;
            acc[n].x += xv.z * wv[2].x; acc[n].y += xv.z * wv[2].y;
            acc[n].x += xv.w * wv[3].x; acc[n].y += xv.w * wv[3].y;
        }
    }

    float as0 = a_src[2 * lane], as1 = a_src[2 * lane + 1];
    float ad0 = a_dst[2 * lane], ad1 = a_dst[2 * lane + 1];
    int head = lane >> 3;
    float vmax = -1e30f;
#pragma unroll
    for (int n = 0; n < 4; n++) {
        int node = nblk + nw + n;
        g_featH[node * 32 + lane] = acc[n];
        float vs = acc[n].x * as0 + acc[n].y * as1;
        float vd = acc[n].x * ad0 + acc[n].y * ad1;
#pragma unroll
        for (int o = 4; o >= 1; o >>= 1) {
            vs += __shfl_xor_sync(0xffffffffu, vs, o, 8);
            vd += __shfl_xor_sync(0xffffffffu, vd, o, 8);
        }
        if ((lane & 7) == 0) {
            ((float*)g_als4)[node * 4 + head] = vs;
            ((float*)g_ald4)[node * 4 + head] = vd;
            vmax = fmaxf(vmax, vs);
        }
    }
    if ((lane & 7) == 0) wm[w][head] = vmax;
    __syncthreads();
    if (w == 0) {
        float v = wm[lane >> 2][lane & 3];
#pragma unroll
        for (int o = 16; o >= 4; o >>= 1)
            v = fmaxf(v, __shfl_xor_sync(0xffffffffu, v, o));
        if (lane < 4) atomicMax(&g_gmaxu[layer * 4 + lane], fenc(v));
    }
}

// ---------------- aggregate core: HALF-WARP per dst ---------------------------
// lanes 0-15 serve dst_a, lanes 16-31 serve dst_b; each lane owns 4 features.
// ps_h: this half's smem float4[16] (p for 4 heads per edge slot).
// Returns relu(acc/sum + bias4) for features 4*hl..4*hl+3.
__device__ __forceinline__ float4 agg_core2(int dst, int layer, int hl, int half,
                                            const float4* __restrict__ bias4,
                                            float4* ps_h) {
    int beg = g_rowptr[dst];
    int deg = g_rowptr[dst + 1] - beg;

    float4 b4 = bias4[hl];
    float4 ald = g_ald4[dst];
    float4 C;
    C.x = lrelu(fdec(g_gmaxu[layer * 4 + 0]) + ald.x);
    C.y = lrelu(fdec(g_gmaxu[layer * 4 + 1]) + ald.y);
    C.z = lrelu(fdec(g_gmaxu[layer * 4 + 2]) + ald.z);
    C.w = lrelu(fdec(g_gmaxu[layer * 4 + 3]) + ald.w);

    // warp-uniform chunk count: max degree of the two halves
    int deg_o = __shfl_xor_sync(0xffffffffu, deg, 16);
    int deg_w = max(deg, deg_o);

    int head = hl >> 2;
    float ssum = 0.f;
    float4 acc = make_float4(0.f, 0.f, 0.f, 0.f);
    const float* pb = (const float*)ps_h;
    const float4* __restrict__ H4 = (const float4*)g_featH;

    for (int base = 0; base < deg_w; base += 16) {
        int i = base + hl;
        bool v = i < deg;
        int si = min(beg + (v ? i : 0), NE - 1);
        int s = g_ssrc[si];
        float4 a = g_als4[s];
        float4 p;
        p.x = v ? __expf(lrelu(a.x + ald.x) - C.x) : 0.f;
        p.y = v ? __expf(lrelu(a.y + ald.y) - C.y) : 0.f;
        p.z = v ? __expf(lrelu(a.z + ald.z) - C.z) : 0.f;
        p.w = v ? __expf(lrelu(a.w + ald.w) - C.w) : 0.f;
        ps_h[hl] = p;
        __syncwarp();

        int hb = half << 4;
#pragma unroll
        for (int jb = 0; jb < 16; jb += 8) {
            int sj[8];
            float pj[8];
            float4 hv[8];
#pragma unroll
            for (int u = 0; u < 8; u++) sj[u] = __shfl_sync(0xffffffffu, s, hb + jb + u);
#pragma unroll
            for (int u = 0; u < 8; u++) pj[u] = pb[(jb + u) * 4 + head];
#pragma unroll
            for (int u = 0; u < 8; u++) hv[u] = H4[sj[u] * 16 + hl];
#pragma unroll
            for (int u = 0; u < 8; u++) {
                acc.x += pj[u] * hv[u].x;
                acc.y += pj[u] * hv[u].y;
                acc.z += pj[u] * hv[u].z;
                acc.w += pj[u] * hv[u].w;
                ssum  += pj[u];
            }
        }
        __syncwarp();
    }

    // deg==0: ssum=0, acc=0 -> acc*inv = 0 -> relu(bias) automatically
    float inv = 1.f / (ssum + 1e-16f);
    return make_float4(fmaxf(acc.x * inv + b4.x, 0.f),
                       fmaxf(acc.y * inv + b4.y, 0.f),
                       fmaxf(acc.z * inv + b4.z, 0.f),
                       fmaxf(acc.w * inv + b4.w, 0.f));
}

// 16 dsts per block (8 warps x 2); grid = N_NODES/16 = 4096
__global__ __launch_bounds__(256) void k_aggregate(const float* __restrict__ bias,
                                                   int layer,
                                                   float4* __restrict__ out4) {
    __shared__ float4 ps[8][2][16];
    int tid  = threadIdx.x;
    int w    = tid >> 5;
    int lane = tid & 31;
    int half = lane >> 4;
    int hl   = lane & 15;
    int dst  = blockIdx.x * 16 + w * 2 + half;

    float4 o = agg_core2(dst, layer, hl, half, (const float4*)bias, ps[w][half]);
    out4[dst * 16 + hl] = o;
}

// layer-2 variant: fused node projection -> writes g_pbuf[n*8+p]
__global__ __launch_bounds__(256) void k_aggregate_proj(const float* __restrict__ bias,
                                                        int layer,
                                                        const float* __restrict__ Wp,
                                                        const float* __restrict__ bp) {
    __shared__ float4 ps[8][2][16];
    __shared__ float Wps[64 * PROJ];
    __shared__ float bps[PROJ];
    int tid  = threadIdx.x;
    int w    = tid >> 5;
    int lane = tid & 31;
    int half = lane >> 4;
    int hl   = lane & 15;
    int dst  = blockIdx.x * 16 + w * 2 + half;

    for (int i = tid; i < 64 * PROJ; i += 256) Wps[i] = Wp[i];
    if (tid < PROJ) bps[tid] = bp[tid];
    __syncthreads();

    float4 o = agg_core2(dst, layer, hl, half, (const float4*)bias, ps[w][half]);

    int f0 = 4 * hl;
    float pr[PROJ];
#pragma unroll
    for (int p = 0; p < PROJ; p++)
        pr[p] = o.x * Wps[(f0 + 0) * PROJ + p] + o.y * Wps[(f0 + 1) * PROJ + p] +
                o.z * Wps[(f0 + 2) * PROJ + p] + o.w * Wps[(f0 + 3) * PROJ + p];
    // reduce across the 16 lanes of this half (xor offsets stay within the half)
#pragma unroll
    for (int off = 8; off >= 1; off >>= 1) {
#pragma unroll
        for (int p = 0; p < PROJ; p++)
            pr[p] += __shfl_xor_sync(0xffffffffu, pr[p], off);
    }
    if (hl == 0) {
        float4 r0 = make_float4(fmaxf(pr[0] + bps[0], 0.f), fmaxf(pr[1] + bps[1], 0.f),
                                fmaxf(pr[2] + bps[2], 0.f), fmaxf(pr[3] + bps[3], 0.f));
        float4 r1 = make_float4(fmaxf(pr[4] + bps[4], 0.f), fmaxf(pr[5] + bps[5], 0.f),
                                fmaxf(pr[6] + bps[6], 0.f), fmaxf(pr[7] + bps[7], 0.f));
        *(float4*)&g_pbuf[dst * PROJ]     = r0;
        *(float4*)&g_pbuf[dst * PROJ + 4] = r1;
    }
}

// ---------------- final GEMM: [512,1024] @ [1024,128] + bf -------------------
__global__ __launch_bounds__(256) void k_final(const float* __restrict__ Wf,
                                               const float* __restrict__ bf,
                                               float* __restrict__ out) {
    __shared__ float As[2 * 1024];
    __shared__ float red[2 * 128];
    int tid = threadIdx.x;
    int r0 = blockIdx.x * 2;
    for (int i = tid; i < 2 * 1024; i += 256) As[i] = g_pbuf[r0 * 1024 + i];
    __syncthreads();

    int col  = tid & 127;
    int half = tid >> 7;
    float acc[2] = {0.f, 0.f};
    int k0 = half * 512;
    for (int k = k0; k < k0 + 512; k += 8) {
#pragma unroll
        for (int kk = 0; kk < 8; kk++) {
            float wv = Wf[(k + kk) * 128 + col];
            acc[0] += As[k + kk] * wv;
            acc[1] += As[1024 + k + kk] * wv;
        }
    }
    if (half == 1) {
        red[col] = acc[0];
        red[128 + col] = acc[1];
    }
    __syncthreads();
    if (half == 0) {
        float bv = bf[col];
        out[r0 * 128 + col]       = acc[0] + red[col] + bv;
        out[(r0 + 1) * 128 + col] = acc[1] + red[128 + col] + bv;
    }
}

// ---------------- launch (champion order; t16 in profiled slot 4) -------------
extern "C" void kernel_launch(void* const* d_in, const int* in_sizes, int n_in,
                              void* d_out, int out_size) {
    const float* x   = (const float*)d_in[0];
    const int*   ei  = (const int*)d_in[1];
    const int*   src = ei;
    const int*   dst = ei + NE;
    const float* W0  = (const float*)d_in[3];
    const float* as0 = (const float*)d_in[4];
    const float* ad0 = (const float*)d_in[5];
    const float* b0  = (const float*)d_in[6];
    const float* W1  = (const float*)d_in[7];
    const float* as1 = (const float*)d_in[8];
    const float* ad1 = (const float*)d_in[9];
    const float* b1  = (const float*)d_in[10];
    const float* W2  = (const float*)d_in[11];
    const float* as2 = (const float*)d_in[12];
    const float* ad2 = (const float*)d_in[13];
    const float* b2  = (const float*)d_in[14];
    const float* Wp  = (const float*)d_in[15];
    const float* bp  = (const float*)d_in[16];
    const float* Wf  = (const float*)d_in[17];
    const float* bf  = (const float*)d_in[18];
    float* out = (float*)d_out;

    k_zero_cnt<<<N_NODES / 256, 256>>>();                              // 1
    k_count<<<NE / 256, 256>>>(dst);                                   // 2
    k_scan1<<<64, 1024>>>();                                           // 3
    k_transform<F_IN><<<N_NODES / 32, 256>>>(x, W0, as0, ad0, 0);      // 4 (profiled)
    k_scan2<<<1, 64>>>();                                              // 5
    k_scan3<<<64, 1024>>>();                                           // 6
    k_scatter<<<NE / 256, 256>>>(src, dst);                            // 7

    k_aggregate<<<N_NODES / 16, 256>>>(b0, 0, (float4*)g_featA);       // 8

    k_transform<HID><<<N_NODES / 32, 256>>>((const float*)g_featA, W1, as1, ad1, 1);
    k_aggregate<<<N_NODES / 16, 256>>>(b1, 1, (float4*)g_featB);

    k_transform<HID><<<N_NODES / 32, 256>>>((const float*)g_featB, W2, as2, ad2, 2);
    k_aggregate_proj<<<N_NODES / 16, 256>>>(b2, 2, Wp, bp);

    k_final<<<BGR / 2, 256>>>(Wf, bf, out);
}

// round 16
// speedup vs baseline: 1.1174x; 1.0029x over previous
#include <cuda_runtime.h>

#define N_NODES 65536
#define NE      1048576
#define F_IN    16
#define HID     64
#define HEADS   4
#define PROJ    8
#define OUTD    128
#define BGR     512

// ---------------- scratch (static device globals; no allocation) -------------
__device__ float2   g_featH[N_NODES * 32];
__device__ float2   g_featA[N_NODES * 32];
__device__ float2   g_featB[N_NODES * 32];
__device__ float4   g_als4[N_NODES];
__device__ float4   g_ald4[N_NODES];
__device__ unsigned g_gmaxu[12];
__device__ int      g_cnt[N_NODES];
__device__ int      g_rowptr[N_NODES + 1];
__device__ int      g_cursor[N_NODES];
__device__ int      g_bsum[64];
__device__ int      g_boff[64];
__device__ int      g_ssrc[NE];
__device__ float    g_pbuf[N_NODES * PROJ];

__device__ __forceinline__ float lrelu(float x) {
    return x > 0.f ? x : 0.2f * x;
}
__device__ __forceinline__ float sel4(float4 v, int h) {
    return h == 0 ? v.x : h == 1 ? v.y : h == 2 ? v.z : v.w;
}
__device__ __forceinline__ unsigned fenc(float f) {
    unsigned u = __float_as_uint(f);
    return (u & 0x80000000u) ? ~u : (u | 0x80000000u);
}
__device__ __forceinline__ float fdec(unsigned u) {
    return (u & 0x80000000u) ? __uint_as_float(u ^ 0x80000000u) : __uint_as_float(~u);
}

// ---------------- CSR build --------------------------------------------------
__global__ void k_zero_cnt() {
    int i = blockIdx.x * blockDim.x + threadIdx.x;
    if (i < N_NODES) g_cnt[i] = 0;
    if (i < 12) g_gmaxu[i] = 0u;
}

__global__ void k_count(const int* __restrict__ dst) {
    int e = blockIdx.x * blockDim.x + threadIdx.x;
    if (e < NE) atomicAdd(&g_cnt[dst[e]], 1);
}

__global__ void k_scan1() {
    __shared__ int sh[1024];
    int b = blockIdx.x, t = threadIdx.x, i = b * 1024 + t;
    int c = g_cnt[i];
    sh[t] = c;
    __syncthreads();
    for (int o = 1; o < 1024; o <<= 1) {
        int v = (t >= o) ? sh[t - o] : 0;
        __syncthreads();
        sh[t] += v;
        __syncthreads();
    }
    g_rowptr[i] = sh[t] - c;
    if (t == 1023) g_bsum[b] = sh[t];
}
__global__ void k_scan2() {
    __shared__ int sh[64];
    int t = threadIdx.x;
    int v = g_bsum[t];
    sh[t] = v;
    __syncthreads();
    for (int o = 1; o < 64; o <<= 1) {
        int u = (t >= o) ? sh[t - o] : 0;
        __syncthreads();
        sh[t] += u;
        __syncthreads();
    }
    g_boff[t] = sh[t] - v;
}
__global__ void k_scan3() {
    int b = blockIdx.x, t = threadIdx.x, i = b * 1024 + t;
    int r = g_rowptr[i] + g_boff[b];
    g_rowptr[i] = r;
    g_cursor[i] = r;
    if (i == 0) g_rowptr[N_NODES] = NE;
}

__global__ void k_scatter(const int* __restrict__ src, const int* __restrict__ dst) {
    int e = blockIdx.x * blockDim.x + threadIdx.x;
    if (e < NE) {
        int d = dst[e];
        int pos = atomicAdd(&g_cursor[d], 1);
        g_ssrc[pos] = src[e];
    }
}

// ---------------- dense transform (unchanged champion) -------------------------
template <int K>
__global__ __launch_bounds__(256) void k_transform(const float* __restrict__ in,
                                                   const float* __restrict__ W,
                                                   const float* __restrict__ a_src,
                                                   const float* __restrict__ a_dst,
                                                   int layer) {
    __shared__ __align__(16) float Ws[K * 64];
    __shared__ __align__(16) float xs[32 * K];
    __shared__ float wm[8][4];
    int tid  = threadIdx.x;
    int w    = tid >> 5;
    int lane = tid & 31;
    int nblk = blockIdx.x * 32;

    for (int i = tid; i < K * 64; i += 256) Ws[i] = W[i];
    for (int i = tid; i < 32 * K; i += 256) xs[i] = in[nblk * K + i];
    __syncthreads();

    float2 acc[4];
#pragma unroll
    for (int n = 0; n < 4; n++) acc[n] = make_float2(0.f, 0.f);

    int nw = w * 4;
#pragma unroll
    for (int k = 0; k < K; k += 4) {
        float2 wv[4];
#pragma unroll
        for (int kk = 0; kk < 4; kk++)
            wv[kk] = *(const float2*)&Ws[(k + kk) * 64 + 2 * lane];
#pragma unroll
        for (int n = 0; n < 4; n++) {
            float4 xv = *(const float4*)&xs[(nw + n) * K + k];
            acc[n].x += xv.x * wv[0].x; acc[n].y += xv.x * wv[0].y;
            acc[n].x += xv.y * wv[1].x; acc[n].y += xv.y * wv[1].y;
            acc[n].x += xv.z * wv[2].x; acc[n].y += xv.z * wv[2].y;
            acc[n].x += xv.w * wv[3].x; acc[n].y += xv.w * wv[3].y;
        }
    }

    float as0 = a_src[2 * lane], as1 = a_src[2 * lane + 1];
    float ad0 = a_dst[2 * lane], ad1 = a_dst[2 * lane + 1];
    int head = lane >> 3;
    float vmax = -1e30f;
#pragma unroll
    for (int n = 0; n < 4; n++) {
        int node = nblk + nw + n;
        g_featH[node * 32 + lane] = acc[n];
        float vs = acc[n].x * as0 + acc[n].y * as1;
        float vd = acc[n].x * ad0 + acc[n].y * ad1;
#pragma unroll
        for (int o = 4; o >= 1; o >>= 1) {
            vs += __shfl_xor_sync(0xffffffffu, vs, o, 8);
            vd += __shfl_xor_sync(0xffffffffu, vd, o, 8);
        }
        if ((lane & 7) == 0) {
            ((float*)g_als4)[node * 4 + head] = vs;
            ((float*)g_ald4)[node * 4 + head] = vd;
            vmax = fmaxf(vmax, vs);
        }
    }
    if ((lane & 7) == 0) wm[w][head] = vmax;
    __syncthreads();
    if (w == 0) {
        float v = wm[lane >> 2][lane & 3];
#pragma unroll
        for (int o = 16; o >= 4; o >>= 1)
            v = fmaxf(v, __shfl_xor_sync(0xffffffffu, v, o));
        if (lane < 4) atomicMax(&g_gmaxu[layer * 4 + lane], fenc(v));
    }
}

// ---------------- aggregate core (R6 winner, byte-identical) ------------------
__device__ __forceinline__ float2 agg_core(int dst, int layer, int w, int lane,
                                           const float* __restrict__ bias,
                                           float4* ps_w) {
    int beg = g_rowptr[dst];
    int deg = g_rowptr[dst + 1] - beg;

    float b0 = bias[2 * lane];
    float b1 = bias[2 * lane + 1];

    if (deg == 0)
        return make_float2(fmaxf(b0, 0.f), fmaxf(b1, 0.f));

    float4 ald = g_ald4[dst];
    float4 C;
    C.x = lrelu(fdec(g_gmaxu[layer * 4 + 0]) + ald.x);
    C.y = lrelu(fdec(g_gmaxu[layer * 4 + 1]) + ald.y);
    C.z = lrelu(fdec(g_gmaxu[layer * 4 + 2]) + ald.z);
    C.w = lrelu(fdec(g_gmaxu[layer * 4 + 3]) + ald.w);

    int head = lane >> 3;
    float4 sum = make_float4(0.f, 0.f, 0.f, 0.f);
    float acc0 = 0.f, acc1 = 0.f;
    const float* pb = (const float*)ps_w;

    for (int base = 0; base < deg; base += 32) {
        int i = base + lane;
        bool v = i < deg;
        int s = g_ssrc[beg + (v ? i : deg - 1)];
        float4 a = g_als4[s];
        float4 p;
        p.x = v ? __expf(lrelu(a.x + ald.x) - C.x) : 0.f;
        p.y = v ? __expf(lrelu(a.y + ald.y) - C.y) : 0.f;
        p.z = v ? __expf(lrelu(a.z + ald.z) - C.z) : 0.f;
        p.w = v ? __expf(lrelu(a.w + ald.w) - C.w) : 0.f;
        sum.x += p.x; sum.y += p.y; sum.z += p.z; sum.w += p.w;
        ps_w[lane] = p;
        __syncwarp();

        int cnt = min(32, deg - base);
        int j = 0;
        for (; j + 8 <= cnt; j += 8) {
            int sj[8];
            float pj[8];
            float2 hv[8];
#pragma unroll
            for (int u = 0; u < 8; u++) sj[u] = __shfl_sync(0xffffffffu, s, j + u);
#pragma unroll
            for (int u = 0; u < 8; u++) pj[u] = pb[(j + u) * 4 + head];
#pragma unroll
            for (int u = 0; u < 8; u++) hv[u] = g_featH[sj[u] * 32 + lane];
#pragma unroll
            for (int u = 0; u < 8; u++) {
                acc0 += pj[u] * hv[u].x;
                acc1 += pj[u] * hv[u].y;
            }
        }
        for (; j + 4 <= cnt; j += 4) {
            int s0 = __shfl_sync(0xffffffffu, s, j + 0);
            int s1 = __shfl_sync(0xffffffffu, s, j + 1);
            int s2 = __shfl_sync(0xffffffffu, s, j + 2);
            int s3 = __shfl_sync(0xffffffffu, s, j + 3);
            float p0 = pb[(j + 0) * 4 + head];
            float p1 = pb[(j + 1) * 4 + head];
            float p2 = pb[(j + 2) * 4 + head];
            float p3 = pb[(j + 3) * 4 + head];
            float2 h0 = g_featH[s0 * 32 + lane];
            float2 h1 = g_featH[s1 * 32 + lane];
            float2 h2 = g_featH[s2 * 32 + lane];
            float2 h3 = g_featH[s3 * 32 + lane];
            acc0 += p0 * h0.x; acc1 += p0 * h0.y;
            acc0 += p1 * h1.x; acc1 += p1 * h1.y;
            acc0 += p2 * h2.x; acc1 += p2 * h2.y;
            acc0 += p3 * h3.x; acc1 += p3 * h3.y;
        }
        for (; j < cnt; j++) {
            int sj = __shfl_sync(0xffffffffu, s, j);
            float pj = pb[j * 4 + head];
            float2 hj = g_featH[sj * 32 + lane];
            acc0 += pj * hj.x; acc1 += pj * hj.y;
        }
        __syncwarp();
    }

#pragma unroll
    for (int o = 16; o >= 1; o >>= 1) {
        sum.x += __shfl_xor_sync(0xffffffffu, sum.x, o);
        sum.y += __shfl_xor_sync(0xffffffffu, sum.y, o);
        sum.z += __shfl_xor_sync(0xffffffffu, sum.z, o);
        sum.w += __shfl_xor_sync(0xffffffffu, sum.w, o);
    }
    float inv = 1.f / (sel4(sum, head) + 1e-16f);
    return make_float2(fmaxf(acc0 * inv + b0, 0.f),
                       fmaxf(acc1 * inv + b1, 0.f));
}

// 2 warps per block: near-zero block-retirement tail (degree-variance theory)
__global__ __launch_bounds__(64) void k_aggregate(const float* __restrict__ bias,
                                                  int layer,
                                                  float2* __restrict__ out) {
    __shared__ float4 ps[2][32];
    int w    = threadIdx.x >> 5;
    int lane = threadIdx.x & 31;
    int dst  = blockIdx.x * 2 + w;
    float2 o = agg_core(dst, layer, w, lane, bias, ps[w]);
    out[dst * 32 + lane] = o;
}

// layer-2 variant: fused node projection -> writes g_pbuf[n*8+p]
__global__ __launch_bounds__(64) void k_aggregate_proj(const float* __restrict__ bias,
                                                       int layer,
                                                       const float* __restrict__ Wp,
                                                       const float* __restrict__ bp) {
    __shared__ float4 ps[2][32];
    __shared__ float Wps[64 * PROJ];
    __shared__ float bps[PROJ];
    int tid  = threadIdx.x;
    int w    = tid >> 5;
    int lane = tid & 31;
    int dst  = blockIdx.x * 2 + w;

    for (int i = tid; i < 64 * PROJ; i += 64) Wps[i] = Wp[i];
    if (tid < PROJ) bps[tid] = bp[tid];
    __syncthreads();

    float2 o = agg_core(dst, layer, w, lane, bias, ps[w]);

    float pr[PROJ];
#pragma unroll
    for (int p = 0; p < PROJ; p++)
        pr[p] = o.x * Wps[(2 * lane) * PROJ + p] + o.y * Wps[(2 * lane + 1) * PROJ + p];
#pragma unroll
    for (int off = 16; off >= 1; off >>= 1) {
#pragma unroll
        for (int p = 0; p < PROJ; p++)
            pr[p] += __shfl_xor_sync(0xffffffffu, pr[p], off);
    }
    if (lane == 0) {
        float4 r0 = make_float4(fmaxf(pr[0] + bps[0], 0.f), fmaxf(pr[1] + bps[1], 0.f),
                                fmaxf(pr[2] + bps[2], 0.f), fmaxf(pr[3] + bps[3], 0.f));
        float4 r1 = make_float4(fmaxf(pr[4] + bps[4], 0.f), fmaxf(pr[5] + bps[5], 0.f),
                                fmaxf(pr[6] + bps[6], 0.f), fmaxf(pr[7] + bps[7], 0.f));
        *(float4*)&g_pbuf[dst * PROJ]     = r0;
        *(float4*)&g_pbuf[dst * PROJ + 4] = r1;
    }
}

// ---------------- final GEMM: [512,1024] @ [1024,128] + bf -------------------
__global__ __launch_bounds__(256) void k_final(const float* __restrict__ Wf,
                                               const float* __restrict__ bf,
                                               float* __restrict__ out) {
    __shared__ float As[2 * 1024];
    __shared__ float red[2 * 128];
    int tid = threadIdx.x;
    int r0 = blockIdx.x * 2;
    for (int i = tid; i < 2 * 1024; i += 256) As[i] = g_pbuf[r0 * 1024 + i];
    __syncthreads();

    int col  = tid & 127;
    int half = tid >> 7;
    float acc[2] = {0.f, 0.f};
    int k0 = half * 512;
    for (int k = k0; k < k0 + 512; k += 8) {
#pragma unroll
        for (int kk = 0; kk < 8; kk++) {
            float wv = Wf[(k + kk) * 128 + col];
            acc[0] += As[k + kk] * wv;
            acc[1] += As[1024 + k + kk] * wv;
        }
    }
    if (half == 1) {
        red[col] = acc[0];
        red[128 + col] = acc[1];
    }
    __syncthreads();
    if (half == 0) {
        float bv = bf[col];
        out[r0 * 128 + col]       = acc[0] + red[col] + bv;
        out[(r0 + 1) * 128 + col] = acc[1] + red[128 + col] + bv;
    }
}

// ---------------- launch (champion order; t16 in profiled slot 4) -------------
extern "C" void kernel_launch(void* const* d_in, const int* in_sizes, int n_in,
                              void* d_out, int out_size) {
    const float* x   = (const float*)d_in[0];
    const int*   ei  = (const int*)d_in[1];
    const int*   src = ei;
    const int*   dst = ei + NE;
    const float* W0  = (const float*)d_in[3];
    const float* as0 = (const float*)d_in[4];
    const float* ad0 = (const float*)d_in[5];
    const float* b0  = (const float*)d_in[6];
    const float* W1  = (const float*)d_in[7];
    const float* as1 = (const float*)d_in[8];
    const float* ad1 = (const float*)d_in[9];
    const float* b1  = (const float*)d_in[10];
    const float* W2  = (const float*)d_in[11];
    const float* as2 = (const float*)d_in[12];
    const float* ad2 = (const float*)d_in[13];
    const float* b2  = (const float*)d_in[14];
    const float* Wp  = (const float*)d_in[15];
    const float* bp  = (const float*)d_in[16];
    const float* Wf  = (const float*)d_in[17];
    const float* bf  = (const float*)d_in[18];
    float* out = (float*)d_out;

    k_zero_cnt<<<N_NODES / 256, 256>>>();                              // 1
    k_count<<<NE / 256, 256>>>(dst);                                   // 2
    k_scan1<<<64, 1024>>>();                                           // 3
    k_transform<F_IN><<<N_NODES / 32, 256>>>(x, W0, as0, ad0, 0);      // 4 (profiled)
    k_scan2<<<1, 64>>>();                                              // 5
    k_scan3<<<64, 1024>>>();                                           // 6
    k_scatter<<<NE / 256, 256>>>(src, dst);                            // 7

    k_aggregate<<<N_NODES / 2, 64>>>(b0, 0, g_featA);                  // 8

    k_transform<HID><<<N_NODES / 32, 256>>>((const float*)g_featA, W1, as1, ad1, 1);
    k_aggregate<<<N_NODES / 2, 64>>>(b1, 1, g_featB);

    k_transform<HID><<<N_NODES / 32, 256>>>((const float*)g_featB, W2, as2, ad2, 2);
    k_aggregate_proj<<<N_NODES / 2, 64>>>(b2, 2, Wp, bp);

    k_final<<<BGR / 2, 256>>>(Wf, bf, out);
}

// round 17
// speedup vs baseline: 1.6231x; 1.4526x over previous
#include <cuda_runtime.h>

#define N_NODES 65536
#define NE      1048576
#define F_IN    16
#define HID     64
#define HEADS   4
#define PROJ    8
#define OUTD    128
#define BGR     512

#define NB   148
#define NTH  1024

// ---------------- scratch (static device globals; no allocation) -------------
__device__ float2   g_featH[N_NODES * 32];
__device__ float2   g_featA[N_NODES * 32];
__device__ float2   g_featB[N_NODES * 32];
__device__ float4   g_als4[N_NODES];
__device__ float4   g_ald4[N_NODES];
__device__ unsigned g_gmaxu[12];
__device__ int      g_cnt[N_NODES];
__device__ int      g_rowptr[N_NODES + 1];
__device__ int      g_cursor[N_NODES];
__device__ int      g_bsum[128];
__device__ int      g_boff[128];
__device__ int      g_ssrc[NE];
__device__ float    g_pbuf[N_NODES * PROJ];
__device__ unsigned g_tick;          // monotonic grid-barrier ticket (never reset)

__device__ __forceinline__ float lrelu(float x) {
    return x > 0.f ? x : 0.2f * x;
}
__device__ __forceinline__ float sel4(float4 v, int h) {
    return h == 0 ? v.x : h == 1 ? v.y : h == 2 ? v.z : v.w;
}
__device__ __forceinline__ unsigned fenc(float f) {
    unsigned u = __float_as_uint(f);
    return (u & 0x80000000u) ? ~u : (u | 0x80000000u);
}
__device__ __forceinline__ float fdec(unsigned u) {
    return (u & 0x80000000u) ? __uint_as_float(u ^ 0x80000000u) : __uint_as_float(~u);
}

// monotonic-ticket grid barrier: all NB blocks co-resident by construction
__device__ __forceinline__ void gbar() {
    __syncthreads();
    if (threadIdx.x == 0) {
        __threadfence();
        unsigned t = atomicAdd(&g_tick, 1u);
        unsigned target = (t / NB + 1u) * NB;
        while (atomicAdd((unsigned*)&g_tick, 0u) < target) { }
        __threadfence();
    }
    __syncthreads();
}

// ---------------- transform phase (grid-stride tiles) -------------------------
template <int K, int NPW>
__device__ void transform_phase(const float* __restrict__ in,
                                const float* __restrict__ W,
                                const float* __restrict__ a_src,
                                const float* __restrict__ a_dst,
                                int layer, char* pool) {
    constexpr int TILE = 32 * NPW;
    float* Ws = (float*)pool;                          // K*64 floats
    float* xs = (float*)(pool + K * 64 * 4);           // TILE*K floats
    int tid = threadIdx.x, w = tid >> 5, lane = tid & 31;

    for (int i = tid; i < K * 64; i += NTH) Ws[i] = W[i];

    float as0 = a_src[2 * lane], as1 = a_src[2 * lane + 1];
    float ad0 = a_dst[2 * lane], ad1 = a_dst[2 * lane + 1];
    int head = lane >> 3;
    float vmax = -1e30f;
    int nw = w * NPW;

    for (int tile = blockIdx.x; tile < N_NODES / TILE; tile += NB) {
        int nblk = tile * TILE;
        __syncthreads();                                // protect xs (and Ws on iter 0)
        for (int i = tid; i < TILE * K; i += NTH) xs[i] = in[nblk * K + i];
        __syncthreads();

        float2 acc[NPW];
#pragma unroll
        for (int n = 0; n < NPW; n++) acc[n] = make_float2(0.f, 0.f);
#pragma unroll
        for (int k = 0; k < K; k += 4) {
            float2 wv[4];
#pragma unroll
            for (int kk = 0; kk < 4; kk++)
                wv[kk] = *(const float2*)&Ws[(k + kk) * 64 + 2 * lane];
#pragma unroll
            for (int n = 0; n < NPW; n++) {
                float4 xv = *(const float4*)&xs[(nw + n) * K + k];
                acc[n].x += xv.x * wv[0].x; acc[n].y += xv.x * wv[0].y;
                acc[n].x += xv.y * wv[1].x; acc[n].y += xv.y * wv[1].y;
                acc[n].x += xv.z * wv[2].x; acc[n].y += xv.z * wv[2].y;
                acc[n].x += xv.w * wv[3].x; acc[n].y += xv.w * wv[3].y;
            }
        }
#pragma unroll
        for (int n = 0; n < NPW; n++) {
            int node = nblk + nw + n;
            g_featH[node * 32 + lane] = acc[n];
            float vs = acc[n].x * as0 + acc[n].y * as1;
            float vd = acc[n].x * ad0 + acc[n].y * ad1;
#pragma unroll
            for (int o = 4; o >= 1; o >>= 1) {
                vs += __shfl_xor_sync(0xffffffffu, vs, o, 8);
                vd += __shfl_xor_sync(0xffffffffu, vd, o, 8);
            }
            if ((lane & 7) == 0) {
                ((float*)g_als4)[node * 4 + head] = vs;
                ((float*)g_ald4)[node * 4 + head] = vd;
            }
            vmax = fmaxf(vmax, vs);                    // broadcast copy per 8-group
        }
    }
    if ((lane & 7) == 0)
        atomicMax(&g_gmaxu[layer * 4 + head], fenc(vmax));
}

// ---------------- aggregate core (champion, byte-identical logic) -------------
__device__ __forceinline__ float2 agg_core(int dst, int layer, int lane,
                                           const float* __restrict__ bias,
                                           float4* ps_w) {
    int beg = g_rowptr[dst];
    int deg = g_rowptr[dst + 1] - beg;

    float b0 = bias[2 * lane];
    float b1 = bias[2 * lane + 1];

    if (deg == 0)
        return make_float2(fmaxf(b0, 0.f), fmaxf(b1, 0.f));

    float4 ald = g_ald4[dst];
    float4 C;
    C.x = lrelu(fdec(g_gmaxu[layer * 4 + 0]) + ald.x);
    C.y = lrelu(fdec(g_gmaxu[layer * 4 + 1]) + ald.y);
    C.z = lrelu(fdec(g_gmaxu[layer * 4 + 2]) + ald.z);
    C.w = lrelu(fdec(g_gmaxu[layer * 4 + 3]) + ald.w);

    int head = lane >> 3;
    float4 sum = make_float4(0.f, 0.f, 0.f, 0.f);
    float acc0 = 0.f, acc1 = 0.f;
    const float* pb = (const float*)ps_w;

    for (int base = 0; base < deg; base += 32) {
        int i = base + lane;
        bool v = i < deg;
        int s = g_ssrc[beg + (v ? i : deg - 1)];
        float4 a = g_als4[s];
        float4 p;
        p.x = v ? __expf(lrelu(a.x + ald.x) - C.x) : 0.f;
        p.y = v ? __expf(lrelu(a.y + ald.y) - C.y) : 0.f;
        p.z = v ? __expf(lrelu(a.z + ald.z) - C.z) : 0.f;
        p.w = v ? __expf(lrelu(a.w + ald.w) - C.w) : 0.f;
        sum.x += p.x; sum.y += p.y; sum.z += p.z; sum.w += p.w;
        ps_w[lane] = p;
        __syncwarp();

        int cnt = min(32, deg - base);
        int j = 0;
        for (; j + 8 <= cnt; j += 8) {
            int sj[8];
            float pj[8];
            float2 hv[8];
#pragma unroll
            for (int u = 0; u < 8; u++) sj[u] = __shfl_sync(0xffffffffu, s, j + u);
#pragma unroll
            for (int u = 0; u < 8; u++) pj[u] = pb[(j + u) * 4 + head];
#pragma unroll
            for (int u = 0; u < 8; u++) hv[u] = g_featH[sj[u] * 32 + lane];
#pragma unroll
            for (int u = 0; u < 8; u++) {
                acc0 += pj[u] * hv[u].x;
                acc1 += pj[u] * hv[u].y;
            }
        }
        for (; j < cnt; j++) {
            int sj = __shfl_sync(0xffffffffu, s, j);
            float pj = pb[j * 4 + head];
            float2 hj = g_featH[sj * 32 + lane];
            acc0 += pj * hj.x; acc1 += pj * hj.y;
        }
        __syncwarp();
    }

#pragma unroll
    for (int o = 16; o >= 1; o >>= 1) {
        sum.x += __shfl_xor_sync(0xffffffffu, sum.x, o);
        sum.y += __shfl_xor_sync(0xffffffffu, sum.y, o);
        sum.z += __shfl_xor_sync(0xffffffffu, sum.z, o);
        sum.w += __shfl_xor_sync(0xffffffffu, sum.w, o);
    }
    float inv = 1.f / (sel4(sum, head) + 1e-16f);
    return make_float2(fmaxf(acc0 * inv + b0, 0.f),
                       fmaxf(acc1 * inv + b1, 0.f));
}

__device__ void agg_phase(const float* __restrict__ bias, int layer,
                          float2* __restrict__ out, char* pool) {
    float4* ps = (float4*)pool;                        // 32 warps x 32 float4 = 16KB
    int tid = threadIdx.x, w = tid >> 5, lane = tid & 31;
    for (int d = blockIdx.x * 32 + w; d < N_NODES; d += NB * 32) {
        float2 o = agg_core(d, layer, lane, bias, ps + w * 32);
        out[d * 32 + lane] = o;
    }
}

__device__ void agg_proj_phase(const float* __restrict__ bias, int layer,
                               const float* __restrict__ Wp,
                               const float* __restrict__ bp, char* pool) {
    float4* ps  = (float4*)pool;                       // 16KB
    float* Wps  = (float*)(pool + 16384);              // 2KB
    float* bps  = (float*)(pool + 16384 + 2048);
    int tid = threadIdx.x, w = tid >> 5, lane = tid & 31;

    for (int i = tid; i < 64 * PROJ; i += NTH) Wps[i] = Wp[i];
    if (tid < PROJ) bps[tid] = bp[tid];
    __syncthreads();

    for (int d = blockIdx.x * 32 + w; d < N_NODES; d += NB * 32) {
        float2 o = agg_core(d, layer, lane, bias, ps + w * 32);
        float pr[PROJ];
#pragma unroll
        for (int p = 0; p < PROJ; p++)
            pr[p] = o.x * Wps[(2 * lane) * PROJ + p] + o.y * Wps[(2 * lane + 1) * PROJ + p];
#pragma unroll
        for (int off = 16; off >= 1; off >>= 1) {
#pragma unroll
            for (int p = 0; p < PROJ; p++)
                pr[p] += __shfl_xor_sync(0xffffffffu, pr[p], off);
        }
        if (lane == 0) {
            float4 r0 = make_float4(fmaxf(pr[0] + bps[0], 0.f), fmaxf(pr[1] + bps[1], 0.f),
                                    fmaxf(pr[2] + bps[2], 0.f), fmaxf(pr[3] + bps[3], 0.f));
            float4 r1 = make_float4(fmaxf(pr[4] + bps[4], 0.f), fmaxf(pr[5] + bps[5], 0.f),
                                    fmaxf(pr[6] + bps[6], 0.f), fmaxf(pr[7] + bps[7], 0.f));
            *(float4*)&g_pbuf[d * PROJ]     = r0;
            *(float4*)&g_pbuf[d * PROJ + 4] = r1;
        }
    }
}

// ---------------- the persistent mega-kernel ----------------------------------
__global__ __launch_bounds__(NTH, 1) void k_mega(
    const float* __restrict__ x,
    const int* __restrict__ src, const int* __restrict__ dst,
    const float* __restrict__ W0, const float* __restrict__ as0,
    const float* __restrict__ ad0, const float* __restrict__ b0,
    const float* __restrict__ W1, const float* __restrict__ as1,
    const float* __restrict__ ad1, const float* __restrict__ b1,
    const float* __restrict__ W2, const float* __restrict__ as2,
    const float* __restrict__ ad2, const float* __restrict__ b2,
    const float* __restrict__ Wp, const float* __restrict__ bp) {

    __shared__ __align__(16) char pool[33 * 1024];
    int tid  = threadIdx.x;
    int bid  = blockIdx.x;
    int gtid = bid * NTH + tid;
    const int GSZ = NB * NTH;

    // P0: zero cnt + gmax
    for (int i = gtid; i < N_NODES; i += GSZ) g_cnt[i] = 0;
    if (gtid < 12) g_gmaxu[gtid] = 0u;
    gbar();

    // P1: count
    for (int e = gtid; e < NE; e += GSZ) atomicAdd(&g_cnt[dst[e]], 1);
    gbar();

    // P2a: chunk scans (128 blocks x 512 nodes)
    if (bid < 128) {
        int* sh = (int*)pool;
        int base = bid * 512;
        int c = (tid < 512) ? g_cnt[base + tid] : 0;
        if (tid < 512) sh[tid] = c;
        __syncthreads();
        for (int o = 1; o < 512; o <<= 1) {
            int v = (tid >= o && tid < 512) ? sh[tid - o] : 0;
            __syncthreads();
            if (tid < 512) sh[tid] += v;
            __syncthreads();
        }
        if (tid < 512) g_rowptr[base + tid] = sh[tid] - c;
        if (tid == 511) g_bsum[bid] = sh[511];
    }
    gbar();

    // P2b: block 0 scans the 128 chunk sums
    if (bid == 0) {
        int* sh = (int*)pool;
        int v0 = (tid < 128) ? g_bsum[tid] : 0;
        if (tid < 128) sh[tid] = v0;
        __syncthreads();
        for (int o = 1; o < 128; o <<= 1) {
            int v = (tid >= o && tid < 128) ? sh[tid - o] : 0;
            __syncthreads();
            if (tid < 128) sh[tid] += v;
            __syncthreads();
        }
        if (tid < 128) g_boff[tid] = sh[tid] - v0;
    }
    gbar();

    // P2c: apply offsets, init cursor
    for (int i = gtid; i < N_NODES; i += GSZ) {
        int r = g_rowptr[i] + g_boff[i >> 9];
        g_rowptr[i] = r;
        g_cursor[i] = r;
    }
    if (gtid == 0) g_rowptr[N_NODES] = NE;
    gbar();

    // P3: scatter
    for (int e = gtid; e < NE; e += GSZ) {
        int d = dst[e];
        g_ssrc[atomicAdd(&g_cursor[d], 1)] = src[e];
    }

    // P4: t16 (independent of scatter; one barrier after both)
    transform_phase<F_IN, 4>(x, W0, as0, ad0, 0, pool + 16384);  // avoid scan residue overlap hazard: scan done
    gbar();

    // P5: agg layer 0
    agg_phase(b0, 0, g_featA, pool);
    gbar();

    // P6: t64 layer 1
    transform_phase<HID, 2>((const float*)g_featA, W1, as1, ad1, 1, pool);
    gbar();

    // P7: agg layer 1
    agg_phase(b1, 1, g_featB, pool);
    gbar();

    // P8: t64 layer 2
    transform_phase<HID, 2>((const float*)g_featB, W2, as2, ad2, 2, pool);
    gbar();

    // P9: agg layer 2 + node projection
    agg_proj_phase(b2, 2, Wp, bp, pool);
}

// ---------------- final GEMM: [512,1024] @ [1024,128] + bf -------------------
__global__ __launch_bounds__(256) void k_final(const float* __restrict__ Wf,
                                               const float* __restrict__ bf,
                                               float* __restrict__ out) {
    __shared__ float As[2 * 1024];
    __shared__ float red[2 * 128];
    int tid = threadIdx.x;
    int r0 = blockIdx.x * 2;
    for (int i = tid; i < 2 * 1024; i += 256) As[i] = g_pbuf[r0 * 1024 + i];
    __syncthreads();

    int col  = tid & 127;
    int half = tid >> 7;
    float acc[2] = {0.f, 0.f};
    int k0 = half * 512;
    for (int k = k0; k < k0 + 512; k += 8) {
#pragma unroll
        for (int kk = 0; kk < 8; kk++) {
            float wv = Wf[(k + kk) * 128 + col];
            acc[0] += As[k + kk] * wv;
            acc[1] += As[1024 + k + kk] * wv;
        }
    }
    if (half == 1) {
        red[col] = acc[0];
        red[128 + col] = acc[1];
    }
    __syncthreads();
    if (half == 0) {
        float bv = bf[col];
        out[r0 * 128 + col]       = acc[0] + red[col] + bv;
        out[(r0 + 1) * 128 + col] = acc[1] + red[128 + col] + bv;
    }
}

// ---------------- launch: 2 kernels total -------------------------------------
extern "C" void kernel_launch(void* const* d_in, const int* in_sizes, int n_in,
                              void* d_out, int out_size) {
    const float* x   = (const float*)d_in[0];
    const int*   ei  = (const int*)d_in[1];
    const int*   src = ei;
    const int*   dst = ei + NE;
    const float* W0  = (const float*)d_in[3];
    const float* as0 = (const float*)d_in[4];
    const float* ad0 = (const float*)d_in[5];
    const float* b0  = (const float*)d_in[6];
    const float* W1  = (const float*)d_in[7];
    const float* as1 = (const float*)d_in[8];
    const float* ad1 = (const float*)d_in[9];
    const float* b1  = (const float*)d_in[10];
    const float* W2  = (const float*)d_in[11];
    const float* as2 = (const float*)d_in[12];
    const float* ad2 = (const float*)d_in[13];
    const float* b2  = (const float*)d_in[14];
    const float* Wp  = (const float*)d_in[15];
    const float* bp  = (const float*)d_in[16];
    const float* Wf  = (const float*)d_in[17];
    const float* bf  = (const float*)d_in[18];
    float* out = (float*)d_out;

    k_mega<<<NB, NTH>>>(x, src, dst,
                        W0, as0, ad0, b0,
                        W1, as1, ad1, b1,
                        W2, as2, ad2, b2,
                        Wp, bp);
    k_final<<<BGR / 2, 256>>>(Wf, bf, out);
}